// round 7
// baseline (speedup 1.0000x reference)
#include <cuda_runtime.h>
#include <cstdint>

static constexpr int E_   = 32;
static constexpr int H_   = 2048;
static constexpr int I_   = 768;
static constexpr int T_   = 2048;
static constexpr int MAXA = 8192;

// tf32 truncation-bias correction (validated R2-R5)
static constexpr float CBIAS = 1.000704f;

// ---------------- scratch ----------------------------------------------------
__device__ int   g_counts[E_];
__device__ int   g_offsets[E_];
__device__ int   g_total;
__device__ int   g_tok[MAXA];
__device__ float g_w[MAXA];
__device__ int   g_inv[T_ * 4];
__device__ float g_act[(size_t)MAXA * I_];
__device__ float g_dout[(size_t)MAXA * H_];

__device__ __forceinline__ uint32_t smem_u32(const void* p) {
    uint32_t a;
    asm("{ .reg .u64 t; cvta.to.shared.u64 t, %1; cvt.u32.u64 %0, t; }" : "=r"(a) : "l"(p));
    return a;
}
__device__ __forceinline__ void cpa16(uint32_t dst, const void* src) {
    asm volatile("cp.async.cg.shared.global [%0], [%1], 16;" :: "r"(dst), "l"(src));
}

// ---------------- routing (known-good) ----------------------------------------
__global__ void route_kernel(const int* __restrict__ ridx,
                             const float* __restrict__ rw) {
    __shared__ int s_cnt[E_], s_cur[E_], s_off[E_];
    int tid = threadIdx.x;
    if (tid < E_) { s_cnt[tid] = 0; s_cur[tid] = 0; }
    __syncthreads();
    for (int t = tid; t < T_; t += blockDim.x) {
        int e0 = ridx[4*t], e1 = ridx[4*t+1], e2 = ridx[4*t+2], e3 = ridx[4*t+3];
        if (e0 != e1 && e0 != e2 && e0 != e3) atomicAdd(&s_cnt[e0], 1);
        if (e1 != e2 && e1 != e3)             atomicAdd(&s_cnt[e1], 1);
        if (e2 != e3)                          atomicAdd(&s_cnt[e2], 1);
        atomicAdd(&s_cnt[e3], 1);
    }
    __syncthreads();
    if (tid == 0) {
        int acc = 0;
        for (int e = 0; e < E_; e++) {
            s_off[e] = acc; g_offsets[e] = acc; g_counts[e] = s_cnt[e];
            acc += s_cnt[e];
        }
        g_total = acc;
    }
    __syncthreads();
    for (int t = tid; t < T_; t += blockDim.x) {
        int ee[4]; float ww[4];
        #pragma unroll
        for (int k = 0; k < 4; k++) { ee[k] = ridx[4*t+k]; ww[k] = rw[4*t+k]; }
        #pragma unroll
        for (int k = 0; k < 4; k++) {
            bool keep = true;
            #pragma unroll
            for (int j = k + 1; j < 4; j++) if (ee[j] == ee[k]) keep = false;
            int pos = -1;
            if (keep) {
                pos = s_off[ee[k]] + atomicAdd(&s_cur[ee[k]], 1);
                g_tok[pos] = t; g_w[pos] = ww[k];
            }
            g_inv[4*t + k] = pos;
        }
    }
}

// ---------------- grouped GEMM: 256-row m-tile, 8 warps of 64x64, 4-stage -----
// FIRST: A = gathered hidden [cnt,2048]; B chunk = 64 gate + 64 up cols;
//        epilogue SwiGLU -> g_act[.., n0..n0+64)
// else : A = g_act [cnt,768]; B chunk = 128 cols; epilogue *w -> g_dout
static constexpr int AS_STRIDE = 36;
static constexpr int AS_BUF    = 256 * AS_STRIDE;   // 9216 u32
static constexpr int BS_STRIDE = 136;
static constexpr int BS_BUF    = 32 * BS_STRIDE;    // 4352 u32
static constexpr int STG       = AS_BUF + BS_BUF;   // 13568 u32 = 54272 B
static constexpr int SMEM_BYTES = 4 * STG * 4;      // 217088 B

template<int KDIM, bool FIRST>
__global__ void __launch_bounds__(256, 1)
moe_gemm(const float* __restrict__ Ain, const float* __restrict__ Bfull) {
    constexpr int NCH    = KDIM / 32;
    constexpr int LDB    = FIRST ? 1536 : 2048;
    constexpr int ROWSPE = FIRST ? 2048 : 768;
    constexpr int NOUT   = FIRST ? 64 : 128;

    extern __shared__ uint32_t sm[];
    const int e   = blockIdx.z;
    const int cnt = g_counts[e];
    const int m0  = blockIdx.y * 256;
    if (m0 >= cnt) return;
    const int off = g_offsets[e];
    const int n0  = blockIdx.x * NOUT;
    const int tid = threadIdx.x;
    const int wid = tid >> 5, lane = tid & 31;
    const uint32_t sbase = smem_u32(sm);

    // ---- A staging: 8 rows/thread, row = p*32 + (tid>>3), seg = tid&7 ----
    const int a_seg = tid & 7;
    const int a_r   = tid >> 3;
    const float* aSrc[8];
    uint32_t aDst[8];
    #pragma unroll
    for (int p = 0; p < 8; p++) {
        int gm = m0 + p * 32 + a_r;
        int rr = (gm < cnt) ? gm : 0;
        aSrc[p] = (FIRST ? Ain + (size_t)g_tok[off + rr] * KDIM
                         : g_act + (size_t)(off + rr) * KDIM) + a_seg * 4;
        aDst[p] = sbase + (uint32_t)((p * 32 + a_r) * AS_STRIDE + a_seg * 4) * 4;
    }
    // ---- B staging: 4 segs/thread; row = tid/32 + 8p, seg = tid%32 (16B) ----
    const int b_seg = tid & 31;
    const int b_r   = tid >> 5;
    const int gcol  = FIRST ? (b_seg < 16 ? n0 + b_seg * 4 : 768 + n0 + (b_seg - 16) * 4)
                            : n0 + b_seg * 4;
    const float* bSrc[4];
    uint32_t bDst[4];
    #pragma unroll
    for (int p = 0; p < 4; p++) {
        int row = b_r + 8 * p;
        bSrc[p] = Bfull + ((size_t)e * ROWSPE + row) * LDB + gcol;
        bDst[p] = sbase + (uint32_t)(AS_BUF + row * BS_STRIDE + b_seg * 4) * 4;
    }

    float acc[4][8][4];
    #pragma unroll
    for (int i = 0; i < 4; i++)
        #pragma unroll
        for (int j = 0; j < 8; j++)
            #pragma unroll
            for (int k = 0; k < 4; k++) acc[i][j][k] = 0.f;

    const int wm = (wid >> 1) * 64;                 // 0/64/128/192
    const int wn = (wid & 1) * (FIRST ? 32 : 64);
    const int qr = lane >> 2;
    const int qk = lane & 3;

    auto load_chunk = [&](int c) {
        const uint32_t so = (uint32_t)(c & 3) * (STG * 4);
        const size_t akc = (size_t)c * 32;
        #pragma unroll
        for (int p = 0; p < 8; p++) cpa16(aDst[p] + so, aSrc[p] + akc);
        const size_t bkc = (size_t)c * 32 * LDB;
        #pragma unroll
        for (int p = 0; p < 4; p++) cpa16(bDst[p] + so, bSrc[p] + bkc);
        asm volatile("cp.async.commit_group;" ::: "memory");
    };

    load_chunk(0); load_chunk(1); load_chunk(2);

    for (int c = 0; c < NCH; c++) {
        int rem = NCH - 1 - c;
        if (rem >= 2)      asm volatile("cp.async.wait_group 2;" ::: "memory");
        else if (rem == 1) asm volatile("cp.async.wait_group 1;" ::: "memory");
        else               asm volatile("cp.async.wait_group 0;" ::: "memory");
        __syncthreads();
        if (c + 3 < NCH) load_chunk(c + 3);

        const uint32_t* As = sm + (c & 3) * STG;
        const uint32_t* Bs = As + AS_BUF;
        #pragma unroll
        for (int kk = 0; kk < 32; kk += 8) {
            uint32_t af[4][4], bf[8][2];
            #pragma unroll
            for (int mi = 0; mi < 4; mi++) {
                int mr = wm + mi * 16 + qr;
                af[mi][0] = As[mr * AS_STRIDE + kk + qk];
                af[mi][1] = As[(mr + 8) * AS_STRIDE + kk + qk];
                af[mi][2] = As[mr * AS_STRIDE + kk + qk + 4];
                af[mi][3] = As[(mr + 8) * AS_STRIDE + kk + qk + 4];
            }
            #pragma unroll
            for (int ni = 0; ni < 8; ni++) {
                int nc = FIRST ? (ni < 4 ? wn + ni * 8 + qr : 64 + wn + (ni - 4) * 8 + qr)
                               : wn + ni * 8 + qr;
                bf[ni][0] = Bs[(kk + qk) * BS_STRIDE + nc];
                bf[ni][1] = Bs[(kk + qk + 4) * BS_STRIDE + nc];
            }
            #pragma unroll
            for (int mi = 0; mi < 4; mi++)
                #pragma unroll
                for (int ni = 0; ni < 8; ni++)
                    asm volatile(
                        "mma.sync.aligned.m16n8k8.row.col.f32.tf32.tf32.f32 "
                        "{%0,%1,%2,%3}, {%4,%5,%6,%7}, {%8,%9}, {%0,%1,%2,%3};"
                        : "+f"(acc[mi][ni][0]), "+f"(acc[mi][ni][1]),
                          "+f"(acc[mi][ni][2]), "+f"(acc[mi][ni][3])
                        : "r"(af[mi][0]), "r"(af[mi][1]),
                          "r"(af[mi][2]), "r"(af[mi][3]),
                          "r"(bf[ni][0]), "r"(bf[ni][1]));
        }
        __syncthreads();
    }

    // ---- epilogue ----
    #pragma unroll
    for (int mi = 0; mi < 4; mi++) {
        #pragma unroll
        for (int half = 0; half < 2; half++) {
            int r  = wm + mi * 16 + qr + half * 8;
            int gm = m0 + r;
            if (gm >= cnt) continue;
            if (FIRST) {
                float* rowp = g_act + (size_t)(off + gm) * I_ + n0;
                #pragma unroll
                for (int ni = 0; ni < 4; ni++) {
                    int nc = wn + ni * 8 + qk * 2;
                    float g0 = acc[mi][ni][half * 2 + 0] * CBIAS;
                    float g1 = acc[mi][ni][half * 2 + 1] * CBIAS;
                    float u0 = acc[mi][ni + 4][half * 2 + 0] * CBIAS;
                    float u1 = acc[mi][ni + 4][half * 2 + 1] * CBIAS;
                    float v0 = u0 * (g0 / (1.f + __expf(-g0)));
                    float v1 = u1 * (g1 / (1.f + __expf(-g1)));
                    *(float2*)(rowp + nc) = make_float2(v0, v1);
                }
            } else {
                float w = g_w[off + gm] * CBIAS;
                float* rowp = g_dout + (size_t)(off + gm) * H_ + n0;
                #pragma unroll
                for (int ni = 0; ni < 8; ni++) {
                    int nc = wn + ni * 8 + qk * 2;
                    *(float2*)(rowp + nc) = make_float2(acc[mi][ni][half * 2 + 0] * w,
                                                        acc[mi][ni][half * 2 + 1] * w);
                }
            }
        }
    }
}

// ---------------- combine ------------------------------------------------------
__global__ void combine_kernel(float* __restrict__ out) {
    int idx = blockIdx.x * blockDim.x + threadIdx.x;
    if (idx >= T_ * H_) return;
    int t = idx >> 11;
    float s = 0.f;
    #pragma unroll
    for (int k = 0; k < 4; k++) {
        int pos = g_inv[4 * t + k];
        if (pos >= 0) s += g_dout[(size_t)pos * H_ + (idx & (H_ - 1))];
    }
    out[idx] = s;
}

// ---------------- launch --------------------------------------------------------
extern "C" void kernel_launch(void* const* d_in, const int* in_sizes, int n_in,
                              void* d_out, int out_size) {
    const float* hs  = (const float*)d_in[0];
    const float* rw  = (const float*)d_in[1];
    const int*   ri  = (const int*)d_in[2];
    const float* gup = (const float*)d_in[4];
    const float* dn  = (const float*)d_in[5];
    float* out = (float*)d_out;

    cudaFuncSetAttribute((const void*)moe_gemm<2048, true>,
                         cudaFuncAttributeMaxDynamicSharedMemorySize, SMEM_BYTES);
    cudaFuncSetAttribute((const void*)moe_gemm<768, false>,
                         cudaFuncAttributeMaxDynamicSharedMemorySize, SMEM_BYTES);

    route_kernel<<<1, 256>>>(ri, rw);

    moe_gemm<2048, true><<<dim3(12, 2, E_), 256, SMEM_BYTES>>>(hs, gup);    // gate_up + SwiGLU
    moe_gemm<768, false><<<dim3(16, 2, E_), 256, SMEM_BYTES>>>(nullptr, dn); // down * w

    combine_kernel<<<(T_ * H_ + 255) / 256, 256>>>(out);
}

// round 8
// speedup vs baseline: 1.6870x; 1.6870x over previous
#include <cuda_runtime.h>
#include <cstdint>

static constexpr int E_   = 32;
static constexpr int H_   = 2048;
static constexpr int I_   = 768;
static constexpr int T_   = 2048;
static constexpr int MAXA = 8192;

// tf32 truncation-bias correction (validated R2-R6)
static constexpr float CBIAS = 1.000704f;

// ---------------- scratch ----------------------------------------------------
__device__ int   g_counts[E_];
__device__ int   g_offsets[E_];
__device__ int   g_total;
__device__ int   g_tok[MAXA];
__device__ float g_w[MAXA];
__device__ int   g_inv[T_ * 4];
__device__ float g_act[(size_t)MAXA * I_];
__device__ float g_dout[(size_t)MAXA * H_];

__device__ __forceinline__ uint32_t smem_u32(const void* p) {
    uint32_t a;
    asm("{ .reg .u64 t; cvta.to.shared.u64 t, %1; cvt.u32.u64 %0, t; }" : "=r"(a) : "l"(p));
    return a;
}
__device__ __forceinline__ void cpa16(uint32_t dst, const void* src) {
    asm volatile("cp.async.cg.shared.global [%0], [%1], 16;" :: "r"(dst), "l"(src));
}

// ---------------- routing (known-good) ----------------------------------------
__global__ void route_kernel(const int* __restrict__ ridx,
                             const float* __restrict__ rw) {
    __shared__ int s_cnt[E_], s_cur[E_], s_off[E_];
    int tid = threadIdx.x;
    if (tid < E_) { s_cnt[tid] = 0; s_cur[tid] = 0; }
    __syncthreads();
    for (int t = tid; t < T_; t += blockDim.x) {
        int e0 = ridx[4*t], e1 = ridx[4*t+1], e2 = ridx[4*t+2], e3 = ridx[4*t+3];
        if (e0 != e1 && e0 != e2 && e0 != e3) atomicAdd(&s_cnt[e0], 1);
        if (e1 != e2 && e1 != e3)             atomicAdd(&s_cnt[e1], 1);
        if (e2 != e3)                          atomicAdd(&s_cnt[e2], 1);
        atomicAdd(&s_cnt[e3], 1);
    }
    __syncthreads();
    if (tid == 0) {
        int acc = 0;
        for (int e = 0; e < E_; e++) {
            s_off[e] = acc; g_offsets[e] = acc; g_counts[e] = s_cnt[e];
            acc += s_cnt[e];
        }
        g_total = acc;
    }
    __syncthreads();
    for (int t = tid; t < T_; t += blockDim.x) {
        int ee[4]; float ww[4];
        #pragma unroll
        for (int k = 0; k < 4; k++) { ee[k] = ridx[4*t+k]; ww[k] = rw[4*t+k]; }
        #pragma unroll
        for (int k = 0; k < 4; k++) {
            bool keep = true;
            #pragma unroll
            for (int j = k + 1; j < 4; j++) if (ee[j] == ee[k]) keep = false;
            int pos = -1;
            if (keep) {
                pos = s_off[ee[k]] + atomicAdd(&s_cur[ee[k]], 1);
                g_tok[pos] = t; g_w[pos] = ww[k];
            }
            g_inv[4*t + k] = pos;
        }
    }
}

// ---------------- grouped GEMM: 128x256 tile, 8 warps of 64x64, 4-stage -------
// Grid: x = m-tile (fastest -> m-tiles of same (n,e) co-resident, B reuse in L2),
//       y = n-tile, z = expert.
// FIRST: A = gathered hidden [cnt,2048]; B cols = gate[n0..n0+128)|up[768+n0..);
//        epilogue = SwiGLU -> g_act[.., n0..n0+128)
// else : A = g_act [cnt,768]; B cols = [n0..n0+256); epilogue *w -> g_dout
static constexpr int AS_STRIDE = 36;
static constexpr int AS_BUF    = 128 * AS_STRIDE;   // 4608 u32
static constexpr int BS_STRIDE = 264;
static constexpr int BS_BUF    = 32 * BS_STRIDE;    // 8448 u32
static constexpr int STG       = AS_BUF + BS_BUF;   // 13056 u32 = 52224 B
static constexpr int SMEM_BYTES = 4 * STG * 4;      // 208896 B

template<int KDIM, bool FIRST>
__global__ void __launch_bounds__(256, 1)
moe_gemm(const float* __restrict__ Ain, const float* __restrict__ Bfull) {
    constexpr int NCH    = KDIM / 32;
    constexpr int LDB    = FIRST ? 1536 : 2048;
    constexpr int ROWSPE = FIRST ? 2048 : 768;
    constexpr int NOUT   = FIRST ? 128 : 256;

    extern __shared__ uint32_t sm[];
    const int e   = blockIdx.z;
    const int cnt = g_counts[e];
    const int m0  = blockIdx.x * 128;   // m fastest
    if (m0 >= cnt) return;
    const int off = g_offsets[e];
    const int n0  = blockIdx.y * NOUT;
    const int tid = threadIdx.x;
    const int wid = tid >> 5, lane = tid & 31;
    const uint32_t sbase = smem_u32(sm);

    // ---- A staging: 4 rows/thread, row = p*32 + (tid>>3), seg = tid&7 ----
    const int a_seg = tid & 7;
    const int a_r   = tid >> 3;
    const float* aSrc[4];
    uint32_t aDst[4];
    #pragma unroll
    for (int p = 0; p < 4; p++) {
        int gm = m0 + p * 32 + a_r;
        int rr = (gm < cnt) ? gm : 0;
        aSrc[p] = (FIRST ? Ain + (size_t)g_tok[off + rr] * KDIM
                         : g_act + (size_t)(off + rr) * KDIM) + a_seg * 4;
        aDst[p] = sbase + (uint32_t)((p * 32 + a_r) * AS_STRIDE + a_seg * 4) * 4;
    }
    // ---- B staging: warp = sub-tile nt (32 cols), seg = tid&7, rb = (tid>>3)&3
    const int b_nt  = tid >> 5;
    const int b_seg = tid & 7;
    const int b_rb  = (tid >> 3) & 3;
    const int gcol  = FIRST ? (b_nt < 4 ? n0 + b_nt * 32 : 768 + n0 + (b_nt - 4) * 32)
                            : n0 + b_nt * 32;
    const float* bSrc = Bfull + ((size_t)e * ROWSPE + b_rb) * LDB + gcol + b_seg * 4;
    const uint32_t bDst0 = sbase + (uint32_t)(AS_BUF + b_rb * BS_STRIDE + b_nt * 32 + b_seg * 4) * 4;

    float acc[4][8][4];
    #pragma unroll
    for (int i = 0; i < 4; i++)
        #pragma unroll
        for (int j = 0; j < 8; j++)
            #pragma unroll
            for (int k = 0; k < 4; k++) acc[i][j][k] = 0.f;

    const int wm = (wid >> 2) * 64;                    // 0 / 64
    const int wn = (wid & 3) * (FIRST ? 32 : 64);      // n within acc layout
    const int qr = lane >> 2;
    const int qk = lane & 3;

    auto load_chunk = [&](int c) {
        const uint32_t so = (uint32_t)(c & 3) * (STG * 4);
        const size_t akc = (size_t)c * 32;
        #pragma unroll
        for (int p = 0; p < 4; p++) cpa16(aDst[p] + so, aSrc[p] + akc);
        const float* bp = bSrc + (size_t)c * 32 * LDB;
        #pragma unroll
        for (int p = 0; p < 8; p++)
            cpa16(bDst0 + so + (uint32_t)(p * 4 * BS_STRIDE) * 4, bp + (size_t)p * 4 * LDB);
        asm volatile("cp.async.commit_group;" ::: "memory");
    };

    load_chunk(0); load_chunk(1); load_chunk(2);

    for (int c = 0; c < NCH; c++) {
        int rem = NCH - 1 - c;
        if (rem >= 2)      asm volatile("cp.async.wait_group 2;" ::: "memory");
        else if (rem == 1) asm volatile("cp.async.wait_group 1;" ::: "memory");
        else               asm volatile("cp.async.wait_group 0;" ::: "memory");
        __syncthreads();
        if (c + 3 < NCH) load_chunk(c + 3);

        const uint32_t* As = sm + (c & 3) * STG;
        const uint32_t* Bs = As + AS_BUF;
        #pragma unroll
        for (int kk = 0; kk < 32; kk += 8) {
            uint32_t af[4][4], bf[8][2];
            #pragma unroll
            for (int mi = 0; mi < 4; mi++) {
                int mr = wm + mi * 16 + qr;
                af[mi][0] = As[mr * AS_STRIDE + kk + qk];
                af[mi][1] = As[(mr + 8) * AS_STRIDE + kk + qk];
                af[mi][2] = As[mr * AS_STRIDE + kk + qk + 4];
                af[mi][3] = As[(mr + 8) * AS_STRIDE + kk + qk + 4];
            }
            #pragma unroll
            for (int ni = 0; ni < 8; ni++) {
                int nc = FIRST ? (ni < 4 ? wn + ni * 8 + qr : 128 + wn + (ni - 4) * 8 + qr)
                               : wn + ni * 8 + qr;
                bf[ni][0] = Bs[(kk + qk) * BS_STRIDE + nc];
                bf[ni][1] = Bs[(kk + qk + 4) * BS_STRIDE + nc];
            }
            #pragma unroll
            for (int mi = 0; mi < 4; mi++)
                #pragma unroll
                for (int ni = 0; ni < 8; ni++)
                    asm volatile(
                        "mma.sync.aligned.m16n8k8.row.col.f32.tf32.tf32.f32 "
                        "{%0,%1,%2,%3}, {%4,%5,%6,%7}, {%8,%9}, {%0,%1,%2,%3};"
                        : "+f"(acc[mi][ni][0]), "+f"(acc[mi][ni][1]),
                          "+f"(acc[mi][ni][2]), "+f"(acc[mi][ni][3])
                        : "r"(af[mi][0]), "r"(af[mi][1]),
                          "r"(af[mi][2]), "r"(af[mi][3]),
                          "r"(bf[ni][0]), "r"(bf[ni][1]));
        }
        __syncthreads();
    }

    // ---- epilogue ----
    #pragma unroll
    for (int mi = 0; mi < 4; mi++) {
        #pragma unroll
        for (int half = 0; half < 2; half++) {
            int r  = wm + mi * 16 + qr + half * 8;
            int gm = m0 + r;
            if (gm >= cnt) continue;
            if (FIRST) {
                float* rowp = g_act + (size_t)(off + gm) * I_ + n0;
                #pragma unroll
                for (int ni = 0; ni < 4; ni++) {
                    int nc = wn + ni * 8 + qk * 2;
                    float g0 = acc[mi][ni][half * 2 + 0] * CBIAS;
                    float g1 = acc[mi][ni][half * 2 + 1] * CBIAS;
                    float u0 = acc[mi][ni + 4][half * 2 + 0] * CBIAS;
                    float u1 = acc[mi][ni + 4][half * 2 + 1] * CBIAS;
                    float v0 = u0 * (g0 / (1.f + __expf(-g0)));
                    float v1 = u1 * (g1 / (1.f + __expf(-g1)));
                    *(float2*)(rowp + nc) = make_float2(v0, v1);
                }
            } else {
                float w = g_w[off + gm] * CBIAS;
                float* rowp = g_dout + (size_t)(off + gm) * H_ + n0;
                #pragma unroll
                for (int ni = 0; ni < 8; ni++) {
                    int nc = wn + ni * 8 + qk * 2;
                    *(float2*)(rowp + nc) = make_float2(acc[mi][ni][half * 2 + 0] * w,
                                                        acc[mi][ni][half * 2 + 1] * w);
                }
            }
        }
    }
}

// ---------------- combine (vectorized float4) ----------------------------------
__global__ void combine_kernel(float4* __restrict__ out) {
    int idx = blockIdx.x * blockDim.x + threadIdx.x;
    if (idx >= T_ * H_ / 4) return;
    int t  = idx >> 9;          // H/4 = 512 float4 per token
    int h4 = idx & 511;
    float4 s = make_float4(0.f, 0.f, 0.f, 0.f);
    #pragma unroll
    for (int k = 0; k < 4; k++) {
        int pos = g_inv[4 * t + k];
        if (pos >= 0) {
            float4 v = *(const float4*)(g_dout + (size_t)pos * H_ + h4 * 4);
            s.x += v.x; s.y += v.y; s.z += v.z; s.w += v.w;
        }
    }
    out[idx] = s;
}

// ---------------- launch --------------------------------------------------------
extern "C" void kernel_launch(void* const* d_in, const int* in_sizes, int n_in,
                              void* d_out, int out_size) {
    const float* hs  = (const float*)d_in[0];
    const float* rw  = (const float*)d_in[1];
    const int*   ri  = (const int*)d_in[2];
    const float* gup = (const float*)d_in[4];
    const float* dn  = (const float*)d_in[5];
    float* out = (float*)d_out;

    cudaFuncSetAttribute((const void*)moe_gemm<2048, true>,
                         cudaFuncAttributeMaxDynamicSharedMemorySize, SMEM_BYTES);
    cudaFuncSetAttribute((const void*)moe_gemm<768, false>,
                         cudaFuncAttributeMaxDynamicSharedMemorySize, SMEM_BYTES);

    route_kernel<<<1, 256>>>(ri, rw);

    // x = m-tile (fastest), y = n-tile, z = expert
    moe_gemm<2048, true><<<dim3(8, 6, E_), 256, SMEM_BYTES>>>(hs, gup);     // gate_up + SwiGLU
    moe_gemm<768, false><<<dim3(8, 8, E_), 256, SMEM_BYTES>>>(nullptr, dn); // down * w

    combine_kernel<<<(T_ * H_ / 4 + 255) / 256, 256>>>((float4*)out);
}